// round 10
// baseline (speedup 1.0000x reference)
#include <cuda_runtime.h>
#include <cuda_bf16.h>
#include <cuda_fp16.h>
#include <cstdint>

#define N_NODES 50000
#define N_EDGES 800000
#define HID 128
#define COUT 40
#define SETUP_BLOCKS 148   // one block per SM: co-residency unconditional
#define NB_SCAN 196        // ceil(50000/256)

typedef unsigned long long ull;

// ---------------- device scratch (static, allocation-free) ----------------
__device__ float g_dis[N_NODES];
__device__ float g_cwa[N_NODES];         // sum over out-edges of dis[col]
__device__ int   g_cnt[N_NODES];
__device__ int   g_off[N_NODES + 1];
__device__ int   g_cur[N_NODES];
__device__ int   g_bsum[NB_SCAN];
__device__ __align__(16) unsigned g_emeta[N_EDGES]; // {fp16 norm | 16-bit src}
__device__ float g_v[HID];               // weighted h2 reduction
__device__ int   g_flag;                 // 1 = edge_index is int64, 0 = int32
__device__ unsigned g_barcnt;            // grid barrier arrive counter (self-reset)
__device__ volatile unsigned g_sense;    // grid barrier phase (monotonic across replays)
__device__ unsigned g_done;              // wred completion counter (self-reset)
__device__ float g_bufA[N_NODES * HID];  // xw bf16 / int2 staging
__device__ float g_bufB[N_NODES * HID];  // h bf16 scratch

// ---------------- small helpers ----------------
__device__ __forceinline__ ull pack2(float lo, float hi) {
    ull r; asm("mov.b64 %0,{%1,%2};" : "=l"(r) : "f"(lo), "f"(hi)); return r;
}
__device__ __forceinline__ void unpack2(ull v, float& lo, float& hi) {
    asm("mov.b64 {%0,%1},%2;" : "=f"(lo), "=f"(hi) : "l"(v));
}
__device__ __forceinline__ ull fma2(ull a, ull b, ull c) {
    ull d; asm("fma.rn.f32x2 %0,%1,%2,%3;" : "=l"(d) : "l"(a), "l"(b), "l"(c)); return d;
}
__device__ __forceinline__ void decode_edge(const void* ei, int e, int& r, int& c) {
    if (g_flag) {
        const long long* p = (const long long*)ei;
        r = (int)p[e];
        c = (int)p[N_EDGES + e];
    } else {
        const int* p = (const int*)ei;
        r = p[e];
        c = p[N_EDGES + e];
    }
}

// Software grid barrier; 148 blocks = 1/SM, co-resident by construction.
__device__ __forceinline__ void grid_bar(unsigned target) {
    __threadfence();           // push this thread's global writes/REDs
    __syncthreads();
    if (threadIdx.x == 0) {
        unsigned my = atomicAdd(&g_barcnt, 1u);
        if (my == SETUP_BLOCKS - 1) {
            g_barcnt = 0;
            __threadfence();
            g_sense = target;
        } else {
            while (g_sense != target) { __nanosleep(64); }
        }
        __threadfence();
    }
    __syncthreads();
}

// ---------------- fused CSR-build (one launch, 4 grid barriers) -----------
__global__ __launch_bounds__(256) void k_setup(const void* __restrict__ ei,
                                               int2* __restrict__ stage)
{
    __shared__ int s[256];
    int tid = threadIdx.x;
    int b = blockIdx.x;
    unsigned base = g_sense;   // stable pre-launch; read before bar 1 can release

    // --- phase 0: zero counters, detect index width ---
    for (int i = b * 256 + tid; i < N_NODES; i += SETUP_BLOCKS * 256) {
        g_cnt[i] = 0;
        g_cwa[i] = 0.f;
    }
    if (b == 0 && tid < HID) g_v[tid] = 0.f;
    if (b == 0 && tid < 32) {
        const unsigned* u = (const unsigned*)ei;
        unsigned nz = (u[2 * tid + 1] != 0u) | (u[2 * (tid + 32) + 1] != 0u);
        unsigned any = __ballot_sync(0xffffffffu, nz);
        if (tid == 0) g_flag = (any == 0u) ? 1 : 0;
    }
    grid_bar(base + 1);

    // --- phase 1: decode + histogram ---
    for (int e = b * 256 + tid; e < N_EDGES; e += SETUP_BLOCKS * 256) {
        int r, c;
        decode_edge(ei, e, r, c);
        stage[e] = make_int2(r, c);
        atomicAdd(&g_cnt[c], 1);
    }
    grid_bar(base + 2);

    // --- phase 2: local scans (grid-stride over 196 chunks) ---
    for (int ch = b; ch < NB_SCAN; ch += SETUP_BLOCKS) {
        int i = ch * 256 + tid;
        int v = (i < N_NODES) ? g_cnt[i] : 0;
        s[tid] = v;
        __syncthreads();
        for (int d = 1; d < 256; d <<= 1) {
            int t = (tid >= d) ? s[tid - d] : 0;
            __syncthreads();
            s[tid] += t;
            __syncthreads();
        }
        if (i < N_NODES) g_off[i] = s[tid] - v;
        if (tid == 255) g_bsum[ch] = s[255];
        __syncthreads();
    }
    grid_bar(base + 3);

    // --- phase 3: every block scans the 196 chunk sums redundantly, then
    //     applies its chunks' prefixes and derives dis/cur ---
    {
        int v = (tid < NB_SCAN) ? g_bsum[tid] : 0;
        s[tid] = v;
        __syncthreads();
        for (int d = 1; d < 256; d <<= 1) {
            int t = (tid >= d) ? s[tid - d] : 0;
            __syncthreads();
            s[tid] += t;
            __syncthreads();
        }
        for (int ch = b; ch < NB_SCAN; ch += SETUP_BLOCKS) {
            int pre = (ch == 0) ? 0 : s[ch - 1];
            int i = ch * 256 + tid;
            if (i < N_NODES) {
                int o = g_off[i] + pre;
                g_off[i] = o;
                g_cur[i] = o;
                g_dis[i] = rsqrtf((float)g_cnt[i] + 1.0f);
            }
            if (i == 0) g_off[N_NODES] = N_EDGES;
        }
    }
    grid_bar(base + 4);

    // --- phase 4: fill CSR + layer-3 collapse weights ---
    for (int e = b * 256 + tid; e < N_EDGES; e += SETUP_BLOCKS * 256) {
        int2 rc = stage[e];
        float dr = g_dis[rc.x], dc = g_dis[rc.y];
        int pos = atomicAdd(&g_cur[rc.y], 1);
        unsigned short hn = __half_as_ushort(__float2half_rn(dr * dc));
        g_emeta[pos] = (unsigned)rc.x | ((unsigned)hn << 16);
        atomicAdd(&g_cwa[rc.x], dc);
    }
}

// ---------------- GEMM: [N,128] @ [128,128] -> xw bf16 ---------------------
// 128x128 tile, 256 threads, 8x8 microtile, packed f32x2 FMA, 2 blocks/SM.
// A input is fp32 (a_bf16=0) or bf16 (a_bf16=1).
__global__ __launch_bounds__(256, 2) void k_gemm128(
    const void* __restrict__ Ain, int a_bf16, const float* __restrict__ W,
    __nv_bfloat16* __restrict__ xwh)
{
    __shared__ float sW[32 * 128];
    __shared__ float sA[32 * 128];   // k-major, row XOR-swizzled

    int tid = threadIdx.x;
    int ty = tid >> 4;
    int tx = tid & 15;
    int rb = blockIdx.x * 128;

    ull acc[8][4];
#pragma unroll
    for (int i = 0; i < 8; i++)
#pragma unroll
        for (int j = 0; j < 4; j++) acc[i][j] = 0ull;

    for (int kk = 0; kk < 4; kk++) {
        __syncthreads();
        {
            const float4* Wg = (const float4*)(W + kk * 32 * 128);
            float4* sW4 = (float4*)sW;
#pragma unroll
            for (int t = 0; t < 4; t++) sW4[tid + t * 256] = Wg[tid + t * 256];
        }
#pragma unroll
        for (int t = 0; t < 4; t++) {
            int idx = tid + t * 256;         // 0..1023
            int row = idx >> 3, q = idx & 7;
            int gr = rb + row;
            float4 v = make_float4(0.f, 0.f, 0.f, 0.f);
            if (gr < N_NODES) {
                if (!a_bf16) {
                    v = ((const float4*)Ain)[gr * 32 + kk * 8 + q];
                } else {
                    uint2 u = ((const uint2*)Ain)[gr * 32 + kk * 8 + q];
                    v.x = __uint_as_float(u.x << 16);
                    v.y = __uint_as_float(u.x & 0xFFFF0000u);
                    v.z = __uint_as_float(u.y << 16);
                    v.w = __uint_as_float(u.y & 0xFFFF0000u);
                }
            }
            int xr = row ^ (q << 2);
            sA[(q * 4 + 0) * 128 + xr] = v.x;
            sA[(q * 4 + 1) * 128 + xr] = v.y;
            sA[(q * 4 + 2) * 128 + xr] = v.z;
            sA[(q * 4 + 3) * 128 + xr] = v.w;
        }
        __syncthreads();
#pragma unroll 4
        for (int kl = 0; kl < 32; kl++) {
            int q = kl >> 2;
            float4 a0 = *(const float4*)&sA[kl * 128 + ((ty * 8) ^ (q << 2))];
            float4 a1 = *(const float4*)&sA[kl * 128 + ((ty * 8 + 4) ^ (q << 2))];
            ulonglong2 w01 = *(const ulonglong2*)&sW[kl * 128 + tx * 8];
            ulonglong2 w23 = *(const ulonglong2*)&sW[kl * 128 + tx * 8 + 4];
            ull wp0 = w01.x, wp1 = w01.y, wp2 = w23.x, wp3 = w23.y;
            float ar[8] = {a0.x, a0.y, a0.z, a0.w, a1.x, a1.y, a1.z, a1.w};
#pragma unroll
            for (int i = 0; i < 8; i++) {
                ull ap = pack2(ar[i], ar[i]);
                acc[i][0] = fma2(ap, wp0, acc[i][0]);
                acc[i][1] = fma2(ap, wp1, acc[i][1]);
                acc[i][2] = fma2(ap, wp2, acc[i][2]);
                acc[i][3] = fma2(ap, wp3, acc[i][3]);
            }
        }
    }

    // epilogue: convert to bf16, one uint4 (8 bf16) store per row slice
    uint4* out4 = (uint4*)xwh;
#pragma unroll
    for (int i = 0; i < 8; i++) {
        int gr = rb + ty * 8 + i;
        if (gr >= N_NODES) continue;
        uint4 st;
        float lo, hi;
        unpack2(acc[i][0], lo, hi);
        { __nv_bfloat162 bb = __float22bfloat162_rn(make_float2(lo, hi)); st.x = *(unsigned*)&bb; }
        unpack2(acc[i][1], lo, hi);
        { __nv_bfloat162 bb = __float22bfloat162_rn(make_float2(lo, hi)); st.y = *(unsigned*)&bb; }
        unpack2(acc[i][2], lo, hi);
        { __nv_bfloat162 bb = __float22bfloat162_rn(make_float2(lo, hi)); st.z = *(unsigned*)&bb; }
        unpack2(acc[i][3], lo, hi);
        { __nv_bfloat162 bb = __float22bfloat162_rn(make_float2(lo, hi)); st.w = *(unsigned*)&bb; }
        out4[gr * 16 + tx] = st;
    }
}

// ---------------- CSR aggregate (warp per node, bf16 in/out) ---------------
__device__ __forceinline__ void acc_bf16(float4& acc, uint2 v, float nw) {
    float f0 = __uint_as_float(v.x << 16);
    float f1 = __uint_as_float(v.x & 0xFFFF0000u);
    float f2 = __uint_as_float(v.y << 16);
    float f3 = __uint_as_float(v.y & 0xFFFF0000u);
    acc.x += f0 * nw; acc.y += f1 * nw; acc.z += f2 * nw; acc.w += f3 * nw;
}
__device__ __forceinline__ float meta_norm(unsigned m) {
    return __half2float(__ushort_as_half((unsigned short)(m >> 16)));
}

__global__ __launch_bounds__(256) void k_agg128(
    const __nv_bfloat16* __restrict__ xwh, const float* __restrict__ bias,
    __nv_bfloat16* __restrict__ h)
{
    int w = blockIdx.x * 8 + (threadIdx.x >> 5);
    int lane = threadIdx.x & 31;
    if (w >= N_NODES) return;
    const uint2* xw2 = (const uint2*)xwh;   // row = 32 uint2 (128 bf16)
    float d = g_dis[w];
    float4 acc = make_float4(0.f, 0.f, 0.f, 0.f);
    acc_bf16(acc, xw2[w * 32 + lane], d * d);
    int beg = g_off[w], end = g_off[w + 1];
    int e = beg;
    while ((e & 3) && e < end) {
        unsigned m = g_emeta[e];
        acc_bf16(acc, xw2[(int)(m & 0xFFFFu) * 32 + lane], meta_norm(m));
        e++;
    }
    for (; e + 4 <= end; e += 4) {
        uint4 mm = *(const uint4*)&g_emeta[e];
        uint2 v0 = xw2[(int)(mm.x & 0xFFFFu) * 32 + lane];
        uint2 v1 = xw2[(int)(mm.y & 0xFFFFu) * 32 + lane];
        uint2 v2 = xw2[(int)(mm.z & 0xFFFFu) * 32 + lane];
        uint2 v3 = xw2[(int)(mm.w & 0xFFFFu) * 32 + lane];
        acc_bf16(acc, v0, meta_norm(mm.x));
        acc_bf16(acc, v1, meta_norm(mm.y));
        acc_bf16(acc, v2, meta_norm(mm.z));
        acc_bf16(acc, v3, meta_norm(mm.w));
    }
    for (; e < end; e++) {
        unsigned m = g_emeta[e];
        acc_bf16(acc, xw2[(int)(m & 0xFFFFu) * 32 + lane], meta_norm(m));
    }
    float4 bb = ((const float4*)bias)[lane];
    acc.x = fmaxf(acc.x + bb.x, 0.f);
    acc.y = fmaxf(acc.y + bb.y, 0.f);
    acc.z = fmaxf(acc.z + bb.z, 0.f);
    acc.w = fmaxf(acc.w + bb.w, 0.f);
    uint2 st;
    __nv_bfloat162 p0 = __float22bfloat162_rn(make_float2(acc.x, acc.y));
    __nv_bfloat162 p1 = __float22bfloat162_rn(make_float2(acc.z, acc.w));
    st.x = *(unsigned*)&p0;
    st.y = *(unsigned*)&p1;
    ((uint2*)h)[w * 32 + lane] = st;
}

// --------- layer-3 collapse + fused finish (last block computes out) -------
#define WRED_BLOCKS ((N_NODES + 127) / 128)   // 391
__global__ __launch_bounds__(256) void k_wred(
    const __nv_bfloat16* __restrict__ h2, const float* __restrict__ W2,
    const float* __restrict__ b2, float* __restrict__ out)
{
    __shared__ float sv[256];
    __shared__ unsigned s_rank;
    int tid = threadIdx.x;
    int k = tid & 127;
    int half = tid >> 7;
    float acc = 0.f;
    int m0 = blockIdx.x * 128;
    int mend = min(m0 + 128, N_NODES);
    for (int m = m0 + half; m < mend; m += 2) {
        float d = g_dis[m];
        float wn = d * (g_cwa[m] + d);
        acc += wn * __bfloat162float(h2[m * HID + k]);
    }
    sv[tid] = acc;
    __syncthreads();
    if (half == 0) atomicAdd(&g_v[k], acc + sv[128 + k]);
    __threadfence();           // push this thread's RED before counting
    __syncthreads();
    if (tid == 0) s_rank = atomicAdd(&g_done, 1u);
    __syncthreads();
    if (s_rank == WRED_BLOCKS - 1) {
        if (tid == 0) g_done = 0;
        __threadfence();
        if (tid < COUT) {
            float a = 0.f;
#pragma unroll 4
            for (int j = 0; j < HID; j++) a += __ldcg(&g_v[j]) * W2[j * COUT + tid];
            out[tid] = b2[tid] + a * (1.0f / (float)N_NODES);
        }
    }
}

// ---------------- launch ----------------------------------------------------
extern "C" void kernel_launch(void* const* d_in, const int* in_sizes, int n_in,
                              void* d_out, int out_size)
{
    const float* x  = (const float*)d_in[0];
    const void*  ei = d_in[1];
    const float* W0 = (const float*)d_in[2];
    const float* b0 = (const float*)d_in[3];
    const float* W1 = (const float*)d_in[4];
    const float* b1 = (const float*)d_in[5];
    const float* W2 = (const float*)d_in[6];
    const float* b2 = (const float*)d_in[7];
    float* out = (float*)d_out;

    float* bufA; cudaGetSymbolAddress((void**)&bufA, g_bufA);
    float* bufB; cudaGetSymbolAddress((void**)&bufB, g_bufB);

    const int gemmBlocks = (N_NODES + 127) / 128;   // 391
    const int aggBlocks  = (N_NODES + 7) / 8;       // 6250

    // --- fused CSR build (1 launch, 4 internal grid barriers) ---
    k_setup<<<SETUP_BLOCKS, 256>>>(ei, (int2*)bufA);

    __nv_bfloat16* xwh = (__nv_bfloat16*)bufA;
    __nv_bfloat16* hb  = (__nv_bfloat16*)bufB;

    // --- layer 1: x (fp32) -> hb (h1, bf16) ---
    k_gemm128<<<gemmBlocks, 256>>>(x, 0, W0, xwh);
    k_agg128<<<aggBlocks, 256>>>(xwh, b0, hb);

    // --- layer 2: hb (bf16) -> hb (h2, bf16) ---
    k_gemm128<<<gemmBlocks, 256>>>(hb, 1, W1, xwh);
    k_agg128<<<aggBlocks, 256>>>(xwh, b1, hb);

    // --- layer 3 (collapsed) + finish fused ---
    k_wred<<<WRED_BLOCKS, 256>>>(hb, W2, b2, out);
}